// round 4
// baseline (speedup 1.0000x reference)
#include <cuda_runtime.h>
#include <math.h>
#include <stdint.h>

#define B_  2
#define S_  2048
#define D_  1024
#define H_  16
#define DK_ 64
#define M_  (B_*S_)   // 4096

// ---------------- scratch (allocation-free rule: device globals) -------------
__device__ float g_qh[(size_t)B_*H_*S_*DK_];      // Q head-split, hi
__device__ float g_ql[(size_t)B_*H_*S_*DK_];      // Q head-split, lo
__device__ float g_kp[(size_t)B_*H_*S_*DK_*2];    // K head-split, (hi,lo) pairs
__device__ float g_vp[(size_t)B_*H_*S_*DK_*2];    // V head-split, (hi,lo) pairs
__device__ float g_ap[(size_t)M_*D_*2];           // attn out [B,S,D], (hi,lo) pairs
__device__ float g_wp[(size_t)4*D_*D_*2];         // Wq,Wk,Wv,Wo packed pairs

// ---------------- helpers -----------------------------------------------------
__device__ __forceinline__ uint32_t smem_to_u32(const void* p) {
    uint32_t a;
    asm("{ .reg .u64 t; cvta.to.shared.u64 t, %1; cvt.u32.u64 %0, t; }"
        : "=r"(a) : "l"(p));
    return a;
}
__device__ __forceinline__ void cp_async16(uint32_t dst, const void* src) {
    asm volatile("cp.async.ca.shared.global [%0], [%1], 16;" :: "r"(dst), "l"(src));
}
#define CP_COMMIT() asm volatile("cp.async.commit_group;" ::: "memory")
#define CP_WAIT(n)  asm volatile("cp.async.wait_group %0;" :: "n"(n) : "memory")

__device__ __forceinline__ void tf32_split(float v, uint32_t& hi, uint32_t& lo) {
    uint32_t h;
    asm("cvt.rna.tf32.f32 %0, %1;" : "=r"(h) : "f"(v));
    float l = v - __uint_as_float(h);
    uint32_t lb;
    asm("cvt.rna.tf32.f32 %0, %1;" : "=r"(lb) : "f"(l));
    hi = h; lo = lb;
}
__device__ __forceinline__ uint32_t tf32_of(float v) {
    uint32_t h;
    asm("cvt.rna.tf32.f32 %0, %1;" : "=r"(h) : "f"(v));
    return h;
}
__device__ __forceinline__ void mma_tf32(float* d, const uint32_t* a, const uint32_t* b) {
    asm volatile("mma.sync.aligned.m16n8k8.row.col.f32.tf32.tf32.f32 "
        "{%0,%1,%2,%3}, {%4,%5,%6,%7}, {%8,%9}, {%0,%1,%2,%3};"
        : "+f"(d[0]), "+f"(d[1]), "+f"(d[2]), "+f"(d[3])
        : "r"(a[0]), "r"(a[1]), "r"(a[2]), "r"(a[3]), "r"(b[0]), "r"(b[1]));
}

// ---------------- W pre-split kernel (packed (hi,lo) pairs) -------------------
__global__ __launch_bounds__(256) void split_pack(const float* __restrict__ src,
                                                  float2* __restrict__ dst)
{
    const size_t i = (size_t)blockIdx.x * 256 + threadIdx.x;   // per float4
    const float4 v = *(const float4*)(src + i * 4);
    uint32_t h, l;
    float2 o[4];
    tf32_split(v.x, h, l); o[0] = make_float2(__uint_as_float(h), __uint_as_float(l));
    tf32_split(v.y, h, l); o[1] = make_float2(__uint_as_float(h), __uint_as_float(l));
    tf32_split(v.z, h, l); o[2] = make_float2(__uint_as_float(h), __uint_as_float(l));
    tf32_split(v.w, h, l); o[3] = make_float2(__uint_as_float(h), __uint_as_float(l));
    float2* d = dst + i * 4;
    *(float4*)(d)     = make_float4(o[0].x, o[0].y, o[1].x, o[1].y);
    *(float4*)(d + 2) = make_float4(o[2].x, o[2].y, o[3].x, o[3].y);
}

// ---------------- input GEMM: C = A @ W^T + bias (3xTF32) ---------------------
// A raw fp32 [4096,1024]; W packed pairs. CTA 128x128, chunk 32, cp.async x2.
// OMODE 1: write hi/lo split arrays (Q).  OMODE 2: write packed pairs (K,V).
#define NF_A (2*128*36)
#define GEMM_IN_SMEM ((2*128*36)*4 + (2*128*36)*8)   // 110592

template<int OMODE>
__global__ __launch_bounds__(256, 2) void gemm_in(const float* __restrict__ A,
                                                  const float2* __restrict__ Wp,
                                                  const float* __restrict__ bias,
                                                  float* __restrict__ C0,
                                                  float* __restrict__ C1)
{
    extern __shared__ float smg[];
    float*  As = smg;                      // [2][128][36] raw floats
    float2* Bp = (float2*)(smg + NF_A);    // [2][128][36] pairs
    const int tid = threadIdx.x, lane = tid & 31, wid = tid >> 5;
    const int g = lane >> 2, c = lane & 3;
    const int wm = (wid & 3)*32, wn = (wid >> 2)*64;
    const int m0 = blockIdx.x*128, n0 = blockIdx.y*128;
    const uint32_t sA = smem_to_u32(As), sB = smem_to_u32(Bp);

    float acc[2][8][4] = {};

    #define GI_LOAD(st, kt) do { \
        _Pragma("unroll") \
        for (int i = 0; i < 4; i++) { \
            const int idx = tid + i*256, row = idx >> 3, c4 = idx & 7; \
            cp_async16(sA + (uint32_t)((((st)*128 + row)*36 + c4*4)*4), \
                       A + (size_t)(m0+row)*D_ + (kt) + c4*4); \
        } \
        _Pragma("unroll") \
        for (int i = 0; i < 8; i++) { \
            const int idx = tid + i*256, row = idx >> 4, ch = idx & 15; \
            cp_async16(sB + (uint32_t)((((st)*128 + row)*36 + ch*2)*8), \
                       Wp + (size_t)(n0+row)*D_ + (kt) + ch*2); \
        } \
    } while (0)

    GI_LOAD(0, 0); CP_COMMIT();

    for (int chk = 0; chk < 32; chk++) {
        const int st = chk & 1;
        if (chk < 31) { GI_LOAD(st^1, (chk+1)*32); CP_COMMIT(); CP_WAIT(1); }
        else CP_WAIT(0);
        __syncthreads();

        const float*  Ast = As + st*128*36;
        const float2* Bst = Bp + st*128*36;
        #pragma unroll
        for (int ks = 0; ks < 4; ks++) {
            const int k8 = ks*8;
            uint32_t ah[2][4], al[2][4];
            #pragma unroll
            for (int mt = 0; mt < 2; mt++)
                #pragma unroll
                for (int e = 0; e < 4; e++)
                    tf32_split(Ast[(wm+mt*16+g+(e&1)*8)*36 + k8 + c + (e>>1)*4],
                               ah[mt][e], al[mt][e]);
            #pragma unroll
            for (int nt = 0; nt < 8; nt++) {
                const float2 b0 = Bst[(wn+nt*8+g)*36 + k8 + c];
                const float2 b1 = Bst[(wn+nt*8+g)*36 + k8 + c + 4];
                uint32_t bh2[2] = {__float_as_uint(b0.x), __float_as_uint(b1.x)};
                uint32_t bl2[2] = {__float_as_uint(b0.y), __float_as_uint(b1.y)};
                #pragma unroll
                for (int mt = 0; mt < 2; mt++) {
                    mma_tf32(acc[mt][nt], ah[mt], bh2);
                    mma_tf32(acc[mt][nt], ah[mt], bl2);
                    mma_tf32(acc[mt][nt], al[mt], bh2);
                }
            }
        }
        __syncthreads();
    }

    #pragma unroll
    for (int mt = 0; mt < 2; mt++)
      #pragma unroll
      for (int hf = 0; hf < 2; hf++) {
        const int m = m0 + wm + mt*16 + g + hf*8;
        #pragma unroll
        for (int nt = 0; nt < 8; nt++) {
            const int n = n0 + wn + nt*8 + c*2;
            const float v0 = acc[mt][nt][hf*2+0] + bias[n];
            const float v1 = acc[mt][nt][hf*2+1] + bias[n+1];
            uint32_t h0, l0, h1, l1;
            tf32_split(v0, h0, l0); tf32_split(v1, h1, l1);
            const int bb = m >> 11, ss = m & (S_-1);
            const int hh = n >> 6,  dk = n & 63;
            const size_t base = (((size_t)bb*H_ + hh)*S_ + ss)*DK_ + dk;
            if (OMODE == 1) {
                *(float2*)(C0 + base) = make_float2(__uint_as_float(h0), __uint_as_float(h1));
                *(float2*)(C1 + base) = make_float2(__uint_as_float(l0), __uint_as_float(l1));
            } else {
                *(float4*)(C0 + base*2) = make_float4(__uint_as_float(h0), __uint_as_float(l0),
                                                      __uint_as_float(h1), __uint_as_float(l1));
            }
        }
      }
}

// ---------------- output GEMM: out = Ap @ Wo^T + bias (all pre-split) ---------
#define GEMM_OUT_SMEM (2*2*128*36*8)   // 147456

__global__ __launch_bounds__(256) void gemm_out(const float2* __restrict__ Ap_g,
                                                const float2* __restrict__ Wp,
                                                const float* __restrict__ bias,
                                                float* __restrict__ C)
{
    extern __shared__ float smg[];
    float2* Ap = (float2*)smg;           // [2][128][36]
    float2* Bp = Ap + 2*128*36;          // [2][128][36]
    const int tid = threadIdx.x, lane = tid & 31, wid = tid >> 5;
    const int g = lane >> 2, c = lane & 3;
    const int wm = (wid & 3)*32, wn = (wid >> 2)*64;
    const int m0 = blockIdx.x*128, n0 = blockIdx.y*128;
    const uint32_t sA = smem_to_u32(Ap), sB = smem_to_u32(Bp);

    float acc[2][8][4] = {};

    #define GO_LOAD(st, kt) do { \
        _Pragma("unroll") \
        for (int i = 0; i < 8; i++) { \
            const int idx = tid + i*256, row = idx >> 4, ch = idx & 15; \
            cp_async16(sA + (uint32_t)((((st)*128 + row)*36 + ch*2)*8), \
                       Ap_g + (size_t)(m0+row)*D_ + (kt) + ch*2); \
            cp_async16(sB + (uint32_t)((((st)*128 + row)*36 + ch*2)*8), \
                       Wp + (size_t)(n0+row)*D_ + (kt) + ch*2); \
        } \
    } while (0)

    GO_LOAD(0, 0); CP_COMMIT();

    for (int chk = 0; chk < 32; chk++) {
        const int st = chk & 1;
        if (chk < 31) { GO_LOAD(st^1, (chk+1)*32); CP_COMMIT(); CP_WAIT(1); }
        else CP_WAIT(0);
        __syncthreads();

        const float2* Ast = Ap + st*128*36;
        const float2* Bst = Bp + st*128*36;
        #pragma unroll
        for (int ks = 0; ks < 4; ks++) {
            const int k8 = ks*8;
            uint32_t ah[2][4], al[2][4];
            #pragma unroll
            for (int mt = 0; mt < 2; mt++)
                #pragma unroll
                for (int e = 0; e < 4; e++) {
                    const float2 a = Ast[(wm+mt*16+g+(e&1)*8)*36 + k8 + c + (e>>1)*4];
                    ah[mt][e] = __float_as_uint(a.x);
                    al[mt][e] = __float_as_uint(a.y);
                }
            #pragma unroll
            for (int nt = 0; nt < 8; nt++) {
                const float2 b0 = Bst[(wn+nt*8+g)*36 + k8 + c];
                const float2 b1 = Bst[(wn+nt*8+g)*36 + k8 + c + 4];
                uint32_t bh2[2] = {__float_as_uint(b0.x), __float_as_uint(b1.x)};
                uint32_t bl2[2] = {__float_as_uint(b0.y), __float_as_uint(b1.y)};
                #pragma unroll
                for (int mt = 0; mt < 2; mt++) {
                    mma_tf32(acc[mt][nt], ah[mt], bh2);
                    mma_tf32(acc[mt][nt], ah[mt], bl2);
                    mma_tf32(acc[mt][nt], al[mt], bh2);
                }
            }
        }
        __syncthreads();
    }

    #pragma unroll
    for (int mt = 0; mt < 2; mt++)
      #pragma unroll
      for (int hf = 0; hf < 2; hf++) {
        const int m = m0 + wm + mt*16 + g + hf*8;
        #pragma unroll
        for (int nt = 0; nt < 8; nt++) {
            const int n = n0 + wn + nt*8 + c*2;
            float2 v;
            v.x = acc[mt][nt][hf*2+0] + bias[n];
            v.y = acc[mt][nt][hf*2+1] + bias[n+1];
            *(float2*)(C + (size_t)m*D_ + n) = v;
        }
      }
}

// ---------------- flash attention: 128 thr, warp=32 rows, K-tile 32 -----------
// Q pre-split (hi cached in regs), K/V packed pairs via cp.async, P via shuffles.
#define ATTN_SMEM (2*128*68*4 + 2*32*68*8)   // 104448

__global__ __launch_bounds__(128, 2) void attn_mma2()
{
    extern __shared__ float sma[];
    float*  Qh = sma;                        // [128][68]
    float*  Ql = Qh + 128*68;                // [128][68]
    float2* Kp = (float2*)(Ql + 128*68);     // [32][68] pairs
    float2* Vp = Kp + 32*68;                 // [32][68] pairs
    const int tid = threadIdx.x, lane = tid & 31, wid = tid >> 5;
    const int g = lane >> 2, c = lane & 3;
    const int wr = wid * 32;
    const int h = blockIdx.y, b = blockIdx.z;
    const int q0 = blockIdx.x * 128;
    const size_t bh_row = ((size_t)b*H_ + h) * S_;
    const float*  qhg = g_qh + bh_row*DK_;
    const float*  qlg = g_ql + bh_row*DK_;
    const float2* kg  = (const float2*)g_kp + bh_row*DK_;
    const float2* vg  = (const float2*)g_vp + bh_row*DK_;
    const uint32_t sQh = smem_to_u32(Qh), sQl = smem_to_u32(Ql);
    const uint32_t sK = smem_to_u32(Kp), sV = smem_to_u32(Vp);

    // prologue: Q (hi+lo) and K/V tile 0
    #pragma unroll
    for (int i = 0; i < 16; i++) {
        const int idx = tid + i*128;            // 0..2047
        const int row = idx >> 4, ch = idx & 15;
        cp_async16(sQh + (uint32_t)((row*68 + ch*4)*4), qhg + (size_t)(q0+row)*DK_ + ch*4);
        cp_async16(sQl + (uint32_t)((row*68 + ch*4)*4), qlg + (size_t)(q0+row)*DK_ + ch*4);
    }
    #pragma unroll
    for (int i = 0; i < 8; i++) {
        const int idx = tid + i*128;            // 0..1023
        const int row = idx >> 5, ch = idx & 31;
        cp_async16(sK + (uint32_t)((row*68 + ch*2)*8), kg + (size_t)row*DK_ + ch*2);
        cp_async16(sV + (uint32_t)((row*68 + ch*2)*8), vg + (size_t)row*DK_ + ch*2);
    }
    CP_COMMIT(); CP_WAIT(0);
    __syncthreads();

    // cache Q-hi fragments in registers (reused 64x)
    uint32_t qh[2][8][4];
    #pragma unroll
    for (int mt = 0; mt < 2; mt++)
      #pragma unroll
      for (int ks = 0; ks < 8; ks++)
        #pragma unroll
        for (int e = 0; e < 4; e++)
            qh[mt][ks][e] = __float_as_uint(
                Qh[(wr+mt*16+g+(e&1)*8)*68 + ks*8 + c + (e>>1)*4]);

    float o[2][8][4] = {};
    float mrun[2][2] = {{-1e30f,-1e30f},{-1e30f,-1e30f}};
    float lrun[2][2] = {{0.f,0.f},{0.f,0.f}};

    for (int t = 0; t < S_/32; t++) {
        // ---- S = (Q K^T)/8 over 32 keys ------------------------------------
        float s[2][4][4] = {};
        #pragma unroll
        for (int ks = 0; ks < 8; ks++) {
            const int k8 = ks*8;
            uint32_t qlr[2][4];
            #pragma unroll
            for (int mt = 0; mt < 2; mt++)
                #pragma unroll
                for (int e = 0; e < 4; e++)
                    qlr[mt][e] = __float_as_uint(
                        Ql[(wr+mt*16+g+(e&1)*8)*68 + k8 + c + (e>>1)*4]);
            #pragma unroll
            for (int nt = 0; nt < 4; nt++) {
                const float2 b0 = Kp[(nt*8+g)*68 + k8 + c];
                const float2 b1 = Kp[(nt*8+g)*68 + k8 + c + 4];
                uint32_t bh2[2] = {__float_as_uint(b0.x), __float_as_uint(b1.x)};
                uint32_t bl2[2] = {__float_as_uint(b0.y), __float_as_uint(b1.y)};
                #pragma unroll
                for (int mt = 0; mt < 2; mt++) {
                    mma_tf32(s[mt][nt], qh[mt][ks], bh2);
                    mma_tf32(s[mt][nt], qh[mt][ks], bl2);
                    mma_tf32(s[mt][nt], qlr[mt],   bh2);
                }
            }
        }

        // ---- online softmax -------------------------------------------------
        uint32_t us[2][4][4];
        #pragma unroll
        for (int mt = 0; mt < 2; mt++) {
            #pragma unroll
            for (int hf = 0; hf < 2; hf++) {
                float mx = -1e30f;
                #pragma unroll
                for (int nt = 0; nt < 4; nt++) {
                    s[mt][nt][hf*2]   *= 0.125f;
                    s[mt][nt][hf*2+1] *= 0.125f;
                    mx = fmaxf(mx, fmaxf(s[mt][nt][hf*2], s[mt][nt][hf*2+1]));
                }
                mx = fmaxf(mx, __shfl_xor_sync(0xffffffffu, mx, 1));
                mx = fmaxf(mx, __shfl_xor_sync(0xffffffffu, mx, 2));
                const float mn = fmaxf(mrun[mt][hf], mx);
                const float corr = __expf(mrun[mt][hf] - mn);
                mrun[mt][hf] = mn;
                float ls = 0.f;
                #pragma unroll
                for (int nt = 0; nt < 4; nt++) {
                    const float e0 = __expf(s[mt][nt][hf*2]   - mn);
                    const float e1 = __expf(s[mt][nt][hf*2+1] - mn);
                    s[mt][nt][hf*2] = e0; s[mt][nt][hf*2+1] = e1;
                    ls += e0 + e1;
                }
                ls += __shfl_xor_sync(0xffffffffu, ls, 1);
                ls += __shfl_xor_sync(0xffffffffu, ls, 2);
                lrun[mt][hf] = lrun[mt][hf]*corr + ls;
                #pragma unroll
                for (int nt = 0; nt < 8; nt++) {
                    o[mt][nt][hf*2]   *= corr;
                    o[mt][nt][hf*2+1] *= corr;
                }
            }
            #pragma unroll
            for (int nt = 0; nt < 4; nt++)
                #pragma unroll
                for (int j = 0; j < 4; j++)
                    us[mt][nt][j] = tf32_of(s[mt][nt][j]);
        }

        // ---- O += P V  (P re-fragmented via shuffles, tf32-only) ------------
        #pragma unroll
        for (int ks = 0; ks < 4; ks++) {
            const int k8 = ks*8;
            const int base = lane & ~3;
            const int s0l = base + (c >> 1), s1l = s0l + 2;
            uint32_t pa[2][4];
            #pragma unroll
            for (int mt = 0; mt < 2; mt++) {
                const uint32_t t00 = __shfl_sync(0xffffffffu, us[mt][ks][0], s0l);
                const uint32_t t01 = __shfl_sync(0xffffffffu, us[mt][ks][1], s0l);
                const uint32_t t10 = __shfl_sync(0xffffffffu, us[mt][ks][2], s0l);
                const uint32_t t11 = __shfl_sync(0xffffffffu, us[mt][ks][3], s0l);
                const uint32_t t20 = __shfl_sync(0xffffffffu, us[mt][ks][0], s1l);
                const uint32_t t21 = __shfl_sync(0xffffffffu, us[mt][ks][1], s1l);
                const uint32_t t30 = __shfl_sync(0xffffffffu, us[mt][ks][2], s1l);
                const uint32_t t31 = __shfl_sync(0xffffffffu, us[mt][ks][3], s1l);
                pa[mt][0] = (c & 1) ? t01 : t00;
                pa[mt][1] = (c & 1) ? t11 : t10;
                pa[mt][2] = (c & 1) ? t21 : t20;
                pa[mt][3] = (c & 1) ? t31 : t30;
            }
            #pragma unroll
            for (int nt = 0; nt < 8; nt++) {
                const float2 v0 = Vp[(k8+c)*68 + nt*8 + g];
                const float2 v1 = Vp[(k8+c+4)*68 + nt*8 + g];
                uint32_t vh2[2] = {__float_as_uint(v0.x), __float_as_uint(v1.x)};
                uint32_t vl2[2] = {__float_as_uint(v0.y), __float_as_uint(v1.y)};
                #pragma unroll
                for (int mt = 0; mt < 2; mt++) {
                    mma_tf32(o[mt][nt], pa[mt], vh2);
                    mma_tf32(o[mt][nt], pa[mt], vl2);
                }
            }
        }

        // ---- load next K/V tile --------------------------------------------
        __syncthreads();
        if (t < S_/32 - 1) {
            const float2* kg2 = kg + (size_t)(t+1)*32*DK_;
            const float2* vg2 = vg + (size_t)(t+1)*32*DK_;
            #pragma unroll
            for (int i = 0; i < 8; i++) {
                const int idx = tid + i*128;
                const int row = idx >> 5, ch = idx & 31;
                cp_async16(sK + (uint32_t)((row*68 + ch*2)*8), kg2 + (size_t)row*DK_ + ch*2);
                cp_async16(sV + (uint32_t)((row*68 + ch*2)*8), vg2 + (size_t)row*DK_ + ch*2);
            }
            CP_COMMIT(); CP_WAIT(0);
        }
        __syncthreads();
    }

    // epilogue: normalize, split, write packed pairs for O-GEMM
    float2* ap = (float2*)g_ap;
    #pragma unroll
    for (int mt = 0; mt < 2; mt++)
      #pragma unroll
      for (int hf = 0; hf < 2; hf++) {
        const int r = q0 + wr + mt*16 + g + hf*8;
        const float inv = 1.f / lrun[mt][hf];
        #pragma unroll
        for (int nt = 0; nt < 8; nt++) {
            const int col = h*DK_ + nt*8 + c*2;
            const float v0 = o[mt][nt][hf*2]   * inv;
            const float v1 = o[mt][nt][hf*2+1] * inv;
            uint32_t h0, l0, h1, l1;
            tf32_split(v0, h0, l0); tf32_split(v1, h1, l1);
            *(float4*)(ap + ((size_t)b*S_ + r)*D_ + col) =
                make_float4(__uint_as_float(h0), __uint_as_float(l0),
                            __uint_as_float(h1), __uint_as_float(l1));
        }
      }
}

// ---------------- launch ------------------------------------------------------
extern "C" void kernel_launch(void* const* d_in, const int* in_sizes, int n_in,
                              void* d_out, int out_size)
{
    (void)in_sizes; (void)n_in; (void)out_size;
    const float* Q  = (const float*)d_in[0];
    const float* K  = (const float*)d_in[1];
    const float* V  = (const float*)d_in[2];
    const float* Wq = (const float*)d_in[3];
    const float* bq = (const float*)d_in[4];
    const float* Wk = (const float*)d_in[5];
    const float* bk = (const float*)d_in[6];
    const float* Wv = (const float*)d_in[7];
    const float* bv = (const float*)d_in[8];
    const float* Wo = (const float*)d_in[9];
    const float* bo = (const float*)d_in[10];
    float* out = (float*)d_out;

    float *qh, *ql, *kp, *vp, *ap, *wp;
    cudaGetSymbolAddress((void**)&qh, g_qh);
    cudaGetSymbolAddress((void**)&ql, g_ql);
    cudaGetSymbolAddress((void**)&kp, g_kp);
    cudaGetSymbolAddress((void**)&vp, g_vp);
    cudaGetSymbolAddress((void**)&ap, g_ap);
    cudaGetSymbolAddress((void**)&wp, g_wp);

    float2* wq_p = (float2*)wp;
    float2* wk_p = wq_p + (size_t)D_*D_;
    float2* wv_p = wk_p + (size_t)D_*D_;
    float2* wo_p = wv_p + (size_t)D_*D_;

    cudaFuncSetAttribute(gemm_in<1>, cudaFuncAttributeMaxDynamicSharedMemorySize, GEMM_IN_SMEM);
    cudaFuncSetAttribute(gemm_in<2>, cudaFuncAttributeMaxDynamicSharedMemorySize, GEMM_IN_SMEM);
    cudaFuncSetAttribute(gemm_out,   cudaFuncAttributeMaxDynamicSharedMemorySize, GEMM_OUT_SMEM);
    cudaFuncSetAttribute(attn_mma2,  cudaFuncAttributeMaxDynamicSharedMemorySize, ATTN_SMEM);

    const int sgrid = (D_*D_) / (256*4);   // 1024
    split_pack<<<sgrid, 256>>>(Wq, wq_p);
    split_pack<<<sgrid, 256>>>(Wk, wk_p);
    split_pack<<<sgrid, 256>>>(Wv, wv_p);
    split_pack<<<sgrid, 256>>>(Wo, wo_p);

    const dim3 gg(M_/128, D_/128);   // 32 x 8
    gemm_in<1><<<gg, 256, GEMM_IN_SMEM>>>(Q, wq_p, bq, qh, ql);
    gemm_in<2><<<gg, 256, GEMM_IN_SMEM>>>(K, wk_p, bk, kp, kp);
    gemm_in<2><<<gg, 256, GEMM_IN_SMEM>>>(V, wv_p, bv, vp, vp);

    attn_mma2<<<dim3(S_/128, H_, B_), 128, ATTN_SMEM>>>();

    gemm_out<<<gg, 256, GEMM_OUT_SMEM>>>((const float2*)ap, wo_p, bo, out);
}

// round 5
// speedup vs baseline: 1.7894x; 1.7894x over previous
#include <cuda_runtime.h>
#include <cuda_fp16.h>
#include <math.h>
#include <stdint.h>

#define B_  2
#define S_  2048
#define D_  1024
#define H_  16
#define DK_ 64
#define M_  (B_*S_)   // 4096

// ---------------- scratch (device globals; h2l2 = uint2{hi half2, lo half2}) --
__device__ uint2 g_qi[(size_t)M_*D_/2];     // split input Q  [4096][512 pairs]
__device__ uint2 g_ki[(size_t)M_*D_/2];
__device__ uint2 g_vi[(size_t)M_*D_/2];
__device__ uint2 g_wq[(size_t)D_*D_/2];     // split weights [1024][512 pairs]
__device__ uint2 g_wk[(size_t)D_*D_/2];
__device__ uint2 g_wv[(size_t)D_*D_/2];
__device__ uint2 g_wo[(size_t)D_*D_/2];
__device__ uint2 g_qp[(size_t)B_*H_*S_*DK_/2];  // Q proj [b,h,s,dk-pair]
__device__ uint2 g_kp[(size_t)B_*H_*S_*DK_/2];  // K proj [b,h,s,dk-pair]
__device__ float g_v [(size_t)B_*H_*S_*DK_];    // V proj f32 [b,h,s,dk]
__device__ uint2 g_vt[(size_t)B_*H_*DK_*S_/2];  // V^T [b,h,dk,s-pair]
__device__ uint2 g_ap[(size_t)M_*D_/2];         // attn out [b*s][d-pair]

// ---------------- helpers -----------------------------------------------------
__device__ __forceinline__ uint32_t smem_to_u32(const void* p) {
    uint32_t a;
    asm("{ .reg .u64 t; cvta.to.shared.u64 t, %1; cvt.u32.u64 %0, t; }"
        : "=r"(a) : "l"(p));
    return a;
}
__device__ __forceinline__ void cp_async16(uint32_t dst, const void* src) {
    asm volatile("cp.async.ca.shared.global [%0], [%1], 16;" :: "r"(dst), "l"(src));
}
#define CP_COMMIT() asm volatile("cp.async.commit_group;" ::: "memory")
#define CP_WAIT(n)  asm volatile("cp.async.wait_group %0;" :: "n"(n) : "memory")

__device__ __forceinline__ uint2 pack_h2l2(float v0, float v1) {
    __half2 hp = __floats2half2_rn(v0, v1);
    const float l0 = v0 - __half2float(__low2half(hp));
    const float l1 = v1 - __half2float(__high2half(hp));
    __half2 lp = __floats2half2_rn(l0, l1);
    uint2 r;
    r.x = *reinterpret_cast<uint32_t*>(&hp);
    r.y = *reinterpret_cast<uint32_t*>(&lp);
    return r;
}

// D(16x8,f32) += A(16x16 f16 row) * B(16x8 f16 col)
__device__ __forceinline__ void mma_f16(float* d, const uint32_t* a, const uint32_t* b) {
    asm volatile("mma.sync.aligned.m16n8k16.row.col.f32.f16.f16.f32 "
        "{%0,%1,%2,%3}, {%4,%5,%6,%7}, {%8,%9}, {%0,%1,%2,%3};"
        : "+f"(d[0]), "+f"(d[1]), "+f"(d[2]), "+f"(d[3])
        : "r"(a[0]), "r"(a[1]), "r"(a[2]), "r"(a[3]), "r"(b[0]), "r"(b[1]));
}

// ---------------- prep: fp32 -> h2l2 (pairs along contiguous axis) ------------
__global__ __launch_bounds__(256) void split_h2l2(const float2* __restrict__ src,
                                                  uint2* __restrict__ dst)
{
    const size_t i = (size_t)blockIdx.x * 256 + threadIdx.x;
    const float2 v = src[i];
    dst[i] = pack_h2l2(v.x, v.y);
}

// ---------------- prep: V [b,h,s,dk] f32 -> V^T [b,h,dk,s-pair] h2l2 ----------
__global__ __launch_bounds__(256) void prep_vt()
{
    __shared__ float tile[32][65];
    const int tid = threadIdx.x;
    const int s0 = blockIdx.x * 32, h = blockIdx.y, b = blockIdx.z;
    const size_t base = (((size_t)b*H_ + h)*S_ + s0) * DK_;
    #pragma unroll
    for (int i = 0; i < 8; i++) {
        const int idx = tid + i*256;
        const int s = idx >> 6, dk = idx & 63;
        tile[s][dk] = g_v[base + (size_t)s*DK_ + dk];
    }
    __syncthreads();
    const size_t obase = (((size_t)b*H_ + h)*DK_) * (S_/2) + s0/2;
    #pragma unroll
    for (int i = 0; i < 4; i++) {
        const int idx = tid + i*256;
        const int dk = idx >> 4, sp = idx & 15;
        g_vt[obase + (size_t)dk*(S_/2) + sp] =
            pack_h2l2(tile[2*sp][dk], tile[2*sp+1][dk]);
    }
}

// ---------------- 3xFP16 GEMM: C = A @ W^T + bias ----------------------------
// A,W pre-split h2l2 [rows][512 pairs]. CTA 128x128, chunk k=32 (16 pairs),
// 2-stage cp.async. 8 warps 4x2, warp 32x64.
// OMODE 0: out pairs head-split (Q/K). 1: out f32 head-split (V). 2: flat f32.
#define PSTR 20                       // pairs per smem row (16 + 4 pad)
#define GSM_STAGE (128*PSTR)          // uint2 per stage
#define GEMM_SMEM (4*GSM_STAGE*8)     // A2 + B2 stages = 81920 B

template<int OMODE>
__global__ __launch_bounds__(256, 2) void gemm_f16(const uint2* __restrict__ Ag,
                                                   const uint2* __restrict__ Wg,
                                                   const float* __restrict__ bias,
                                                   float* __restrict__ Cf,
                                                   uint2* __restrict__ Cp)
{
    extern __shared__ uint2 smu[];
    uint2* As = smu;                  // [2][128][PSTR]
    uint2* Bs = smu + 2*GSM_STAGE;
    const int tid = threadIdx.x, lane = tid & 31, wid = tid >> 5;
    const int g = lane >> 2, c = lane & 3;
    const int wm = (wid & 3)*32, wn = (wid >> 2)*64;
    const int m0 = blockIdx.x*128, n0 = blockIdx.y*128;
    const uint32_t sA = smem_to_u32(As), sB = smem_to_u32(Bs);

    float acc[2][8][4] = {};

    #define G_LOAD(st, chk) do { \
        _Pragma("unroll") \
        for (int i = 0; i < 4; i++) { \
            const int idx = tid + i*256, row = idx >> 3, ch = idx & 7; \
            cp_async16(sA + (uint32_t)((((st)*128+row)*PSTR + ch*2)*8), \
                       Ag + (size_t)(m0+row)*512 + (chk)*16 + ch*2); \
            cp_async16(sB + (uint32_t)((((st)*128+row)*PSTR + ch*2)*8), \
                       Wg + (size_t)(n0+row)*512 + (chk)*16 + ch*2); \
        } \
    } while (0)

    G_LOAD(0, 0); CP_COMMIT();

    for (int chk = 0; chk < 32; chk++) {
        const int st = chk & 1;
        if (chk < 31) { G_LOAD(st^1, chk+1); CP_COMMIT(); CP_WAIT(1); }
        else CP_WAIT(0);
        __syncthreads();

        const uint2* Ast = As + st*GSM_STAGE;
        const uint2* Bst = Bs + st*GSM_STAGE;
        #pragma unroll
        for (int ks = 0; ks < 2; ks++) {
            const int p0 = ks*8 + c, p1 = p0 + 4;
            uint32_t ah[2][4], al[2][4];
            #pragma unroll
            for (int mt = 0; mt < 2; mt++) {
                const uint2 a0 = Ast[(wm+mt*16+g  )*PSTR + p0];
                const uint2 a1 = Ast[(wm+mt*16+g+8)*PSTR + p0];
                const uint2 a2 = Ast[(wm+mt*16+g  )*PSTR + p1];
                const uint2 a3 = Ast[(wm+mt*16+g+8)*PSTR + p1];
                ah[mt][0]=a0.x; ah[mt][1]=a1.x; ah[mt][2]=a2.x; ah[mt][3]=a3.x;
                al[mt][0]=a0.y; al[mt][1]=a1.y; al[mt][2]=a2.y; al[mt][3]=a3.y;
            }
            #pragma unroll
            for (int nt = 0; nt < 8; nt++) {
                const uint2 b0 = Bst[(wn+nt*8+g)*PSTR + p0];
                const uint2 b1 = Bst[(wn+nt*8+g)*PSTR + p1];
                uint32_t bh[2] = {b0.x, b1.x};
                uint32_t bl[2] = {b0.y, b1.y};
                #pragma unroll
                for (int mt = 0; mt < 2; mt++) {
                    mma_f16(acc[mt][nt], ah[mt], bh);
                    mma_f16(acc[mt][nt], ah[mt], bl);
                    mma_f16(acc[mt][nt], al[mt], bh);
                }
            }
        }
        __syncthreads();
    }
    #undef G_LOAD

    #pragma unroll
    for (int mt = 0; mt < 2; mt++)
      #pragma unroll
      for (int hf = 0; hf < 2; hf++) {
        const int m = m0 + wm + mt*16 + g + hf*8;
        #pragma unroll
        for (int nt = 0; nt < 8; nt++) {
            const int n = n0 + wn + nt*8 + c*2;
            const float v0 = acc[mt][nt][hf*2+0] + bias[n];
            const float v1 = acc[mt][nt][hf*2+1] + bias[n+1];
            if (OMODE == 2) {
                *(float2*)(Cf + (size_t)m*D_ + n) = make_float2(v0, v1);
            } else {
                const int bb = m >> 11, ss = m & (S_-1);
                const int hh = n >> 6,  dk = n & 63;
                if (OMODE == 0) {
                    Cp[(((size_t)bb*H_ + hh)*S_ + ss)*32 + (dk >> 1)] = pack_h2l2(v0, v1);
                } else {
                    *(float2*)(Cf + (((size_t)bb*H_ + hh)*S_ + ss)*DK_ + dk) =
                        make_float2(v0, v1);
                }
            }
        }
      }
}

// ---------------- fp16 flash attention ----------------------------------------
// 256 thr, 8 warps x 16 q-rows, q-tile 128, k-tile 64, 2-stage K/V cp.async.
// QK: 3-term (hh+hl+lh). P: single fp16 from regs (acc layout == A-frag layout).
// PV: P * (Vh + Vl) = 2 mma.
#define ASTR 36                       // pairs per smem row (32 + 4 pad)
#define ATTN_SMEM ((128*ASTR + 4*64*ASTR)*8)   // 110592 B

__global__ __launch_bounds__(256, 2) void attn_f16()
{
    extern __shared__ uint2 smu[];
    uint2* Qp = smu;                      // [128][ASTR]
    uint2* Kp = smu + 128*ASTR;           // [2][64][ASTR]
    uint2* Vp = Kp + 2*64*ASTR;           // [2][64][ASTR]
    const int tid = threadIdx.x, lane = tid & 31, wid = tid >> 5;
    const int g = lane >> 2, c = lane & 3;
    const int wr = wid * 16;
    const int h = blockIdx.y, b = blockIdx.z;
    const int q0 = blockIdx.x * 128;
    const size_t bh = (size_t)b*H_ + h;
    const uint2* qg  = g_qp + (bh*S_ + q0)*32;
    const uint2* kg  = g_kp + bh*S_*32;
    const uint2* vtg = g_vt + bh*DK_*(S_/2);
    const uint32_t sQ = smem_to_u32(Qp), sK = smem_to_u32(Kp), sV = smem_to_u32(Vp);

    // prologue: Q + K/V tile 0 (one commit group)
    #pragma unroll
    for (int i = 0; i < 8; i++) {
        const int idx = tid + i*256;
        const int row = idx >> 4, ch = idx & 15;
        cp_async16(sQ + (uint32_t)((row*ASTR + ch*2)*8), qg + (size_t)row*32 + ch*2);
    }
    #pragma unroll
    for (int i = 0; i < 4; i++) {
        const int idx = tid + i*256;
        const int row = idx >> 4, ch = idx & 15;
        cp_async16(sK + (uint32_t)((row*ASTR + ch*2)*8), kg + (size_t)row*32 + ch*2);
        cp_async16(sV + (uint32_t)((row*ASTR + ch*2)*8), vtg + (size_t)row*(S_/2) + ch*2);
    }
    CP_COMMIT();

    float o[8][4] = {};
    float mrun[2] = {-1e30f, -1e30f};
    float lrun[2] = {0.f, 0.f};

    for (int t = 0; t < S_/64; t++) {
        const int st = t & 1;
        if (t < S_/64 - 1) {
            const int s2 = st ^ 1;
            #pragma unroll
            for (int i = 0; i < 4; i++) {
                const int idx = tid + i*256;
                const int row = idx >> 4, ch = idx & 15;
                cp_async16(sK + (uint32_t)((((s2*64)+row)*ASTR + ch*2)*8),
                           kg + (size_t)((t+1)*64 + row)*32 + ch*2);
                cp_async16(sV + (uint32_t)((((s2*64)+row)*ASTR + ch*2)*8),
                           vtg + (size_t)row*(S_/2) + (t+1)*32 + ch*2);
            }
            CP_COMMIT(); CP_WAIT(1);
        } else {
            CP_WAIT(0);
        }
        __syncthreads();

        const uint2* Kst = Kp + st*64*ASTR;
        const uint2* Vst = Vp + st*64*ASTR;

        // ---- S = (Q K^T)/8 --------------------------------------------------
        float s[8][4] = {};
        #pragma unroll
        for (int ks = 0; ks < 4; ks++) {
            const int p0 = ks*8 + c, p1 = p0 + 4;
            const uint2 a0 = Qp[(wr+g  )*ASTR + p0];
            const uint2 a1 = Qp[(wr+g+8)*ASTR + p0];
            const uint2 a2 = Qp[(wr+g  )*ASTR + p1];
            const uint2 a3 = Qp[(wr+g+8)*ASTR + p1];
            uint32_t ah[4] = {a0.x, a1.x, a2.x, a3.x};
            uint32_t al[4] = {a0.y, a1.y, a2.y, a3.y};
            #pragma unroll
            for (int nt = 0; nt < 8; nt++) {
                const uint2 b0 = Kst[(nt*8+g)*ASTR + p0];
                const uint2 b1 = Kst[(nt*8+g)*ASTR + p1];
                uint32_t bh2[2] = {b0.x, b1.x};
                uint32_t bl2[2] = {b0.y, b1.y};
                mma_f16(s[nt], ah, bh2);
                mma_f16(s[nt], ah, bl2);
                mma_f16(s[nt], al, bh2);
            }
        }

        // ---- online softmax (rows g, g+8; stats across 4 c-lanes) -----------
        #pragma unroll
        for (int hf = 0; hf < 2; hf++) {
            float mx = -1e30f;
            #pragma unroll
            for (int nt = 0; nt < 8; nt++) {
                s[nt][hf*2]   *= 0.125f;
                s[nt][hf*2+1] *= 0.125f;
                mx = fmaxf(mx, fmaxf(s[nt][hf*2], s[nt][hf*2+1]));
            }
            mx = fmaxf(mx, __shfl_xor_sync(0xffffffffu, mx, 1));
            mx = fmaxf(mx, __shfl_xor_sync(0xffffffffu, mx, 2));
            const float mn = fmaxf(mrun[hf], mx);
            const float corr = __expf(mrun[hf] - mn);
            mrun[hf] = mn;
            float ls = 0.f;
            #pragma unroll
            for (int nt = 0; nt < 8; nt++) {
                const float e0 = __expf(s[nt][hf*2]   - mn);
                const float e1 = __expf(s[nt][hf*2+1] - mn);
                s[nt][hf*2] = e0; s[nt][hf*2+1] = e1;
                ls += e0 + e1;
            }
            ls += __shfl_xor_sync(0xffffffffu, ls, 1);
            ls += __shfl_xor_sync(0xffffffffu, ls, 2);
            lrun[hf] = lrun[hf]*corr + ls;
            #pragma unroll
            for (int nt = 0; nt < 8; nt++) {
                o[nt][hf*2]   *= corr;
                o[nt][hf*2+1] *= corr;
            }
        }

        // ---- P fragments directly from acc registers ------------------------
        uint32_t pa[4][4];
        #pragma unroll
        for (int kv = 0; kv < 4; kv++) {
            __half2 h0 = __floats2half2_rn(s[2*kv  ][0], s[2*kv  ][1]);
            __half2 h1 = __floats2half2_rn(s[2*kv  ][2], s[2*kv  ][3]);
            __half2 h2 = __floats2half2_rn(s[2*kv+1][0], s[2*kv+1][1]);
            __half2 h3 = __floats2half2_rn(s[2*kv+1][2], s[2*kv+1][3]);
            pa[kv][0] = *reinterpret_cast<uint32_t*>(&h0);
            pa[kv][1] = *reinterpret_cast<uint32_t*>(&h1);
            pa[kv][2] = *reinterpret_cast<uint32_t*>(&h2);
            pa[kv][3] = *reinterpret_cast<uint32_t*>(&h3);
        }

        // ---- O += P V (V 2-term) --------------------------------------------
        #pragma unroll
        for (int kv = 0; kv < 4; kv++) {
            const int p0 = kv*8 + c, p1 = p0 + 4;
            #pragma unroll
            for (int nt = 0; nt < 8; nt++) {
                const uint2 v0 = Vst[(nt*8+g)*ASTR + p0];
                const uint2 v1 = Vst[(nt*8+g)*ASTR + p1];
                uint32_t vh2[2] = {v0.x, v1.x};
                uint32_t vl2[2] = {v0.y, v1.y};
                mma_f16(o[nt], pa[kv], vh2);
                mma_f16(o[nt], pa[kv], vl2);
            }
        }
        __syncthreads();
    }

    // epilogue: normalize, split, store h2l2 pairs for the O-GEMM
    #pragma unroll
    for (int hf = 0; hf < 2; hf++) {
        const int r = q0 + wr + g + hf*8;
        const float inv = 1.f / lrun[hf];
        #pragma unroll
        for (int nt = 0; nt < 8; nt++) {
            const int pairidx = h*32 + nt*4 + c;
            g_ap[((size_t)b*S_ + r)*512 + pairidx] =
                pack_h2l2(o[nt][hf*2]*inv, o[nt][hf*2+1]*inv);
        }
    }
}

// ---------------- launch ------------------------------------------------------
extern "C" void kernel_launch(void* const* d_in, const int* in_sizes, int n_in,
                              void* d_out, int out_size)
{
    (void)in_sizes; (void)n_in; (void)out_size;
    const float* Q  = (const float*)d_in[0];
    const float* K  = (const float*)d_in[1];
    const float* V  = (const float*)d_in[2];
    const float* Wq = (const float*)d_in[3];
    const float* bq = (const float*)d_in[4];
    const float* Wk = (const float*)d_in[5];
    const float* bk = (const float*)d_in[6];
    const float* Wv = (const float*)d_in[7];
    const float* bv = (const float*)d_in[8];
    const float* Wo = (const float*)d_in[9];
    const float* bo = (const float*)d_in[10];
    float* out = (float*)d_out;

    uint2 *qi, *ki, *vi, *wq, *wk, *wv, *wo, *qp, *kp, *ap;
    float *vf;
    cudaGetSymbolAddress((void**)&qi, g_qi);
    cudaGetSymbolAddress((void**)&ki, g_ki);
    cudaGetSymbolAddress((void**)&vi, g_vi);
    cudaGetSymbolAddress((void**)&wq, g_wq);
    cudaGetSymbolAddress((void**)&wk, g_wk);
    cudaGetSymbolAddress((void**)&wv, g_wv);
    cudaGetSymbolAddress((void**)&wo, g_wo);
    cudaGetSymbolAddress((void**)&qp, g_qp);
    cudaGetSymbolAddress((void**)&kp, g_kp);
    cudaGetSymbolAddress((void**)&ap, g_ap);
    cudaGetSymbolAddress((void**)&vf, g_v);

    cudaFuncSetAttribute(gemm_f16<0>, cudaFuncAttributeMaxDynamicSharedMemorySize, GEMM_SMEM);
    cudaFuncSetAttribute(gemm_f16<1>, cudaFuncAttributeMaxDynamicSharedMemorySize, GEMM_SMEM);
    cudaFuncSetAttribute(gemm_f16<2>, cudaFuncAttributeMaxDynamicSharedMemorySize, GEMM_SMEM);
    cudaFuncSetAttribute(attn_f16,    cudaFuncAttributeMaxDynamicSharedMemorySize, ATTN_SMEM);

    // pre-split weights (1M elems -> 512K pairs) and inputs (4M -> 2M pairs)
    split_h2l2<<<2048, 256>>>((const float2*)Wq, wq);
    split_h2l2<<<2048, 256>>>((const float2*)Wk, wk);
    split_h2l2<<<2048, 256>>>((const float2*)Wv, wv);
    split_h2l2<<<2048, 256>>>((const float2*)Wo, wo);
    split_h2l2<<<8192, 256>>>((const float2*)Q, qi);
    split_h2l2<<<8192, 256>>>((const float2*)K, ki);
    split_h2l2<<<8192, 256>>>((const float2*)V, vi);

    const dim3 gg(M_/128, D_/128);   // 32 x 8
    gemm_f16<0><<<gg, 256, GEMM_SMEM>>>(qi, wq, bq, nullptr, qp);
    gemm_f16<0><<<gg, 256, GEMM_SMEM>>>(ki, wk, bk, nullptr, kp);
    gemm_f16<1><<<gg, 256, GEMM_SMEM>>>(vi, wv, bv, vf, nullptr);

    prep_vt<<<dim3(S_/32, H_, B_), 256>>>();

    attn_f16<<<dim3(S_/128, H_, B_), 256, ATTN_SMEM>>>();

    gemm_f16<2><<<gg, 256, GEMM_SMEM>>>(ap, wo, bo, out, nullptr);
}

// round 6
// speedup vs baseline: 1.8465x; 1.0319x over previous
#include <cuda_runtime.h>
#include <cuda_fp16.h>
#include <math.h>
#include <stdint.h>

#define B_  2
#define S_  2048
#define D_  1024
#define H_  16
#define DK_ 64
#define M_  (B_*S_)   // 4096

// ---------------- scratch (device globals; h2l2 = uint2{hi half2, lo half2}) --
__device__ uint2 g_qi[(size_t)M_*D_/2];     // split input Q  [4096][512 pairs]
__device__ uint2 g_ki[(size_t)M_*D_/2];
__device__ uint2 g_vi[(size_t)M_*D_/2];
__device__ uint2 g_wq[(size_t)D_*D_/2];     // split weights [1024][512 pairs]
__device__ uint2 g_wk[(size_t)D_*D_/2];
__device__ uint2 g_wv[(size_t)D_*D_/2];
__device__ uint2 g_wo[(size_t)D_*D_/2];
__device__ uint2 g_qp[(size_t)B_*H_*S_*DK_/2];  // Q proj [b,h,s,dk-pair]
__device__ uint2 g_kp[(size_t)B_*H_*S_*DK_/2];  // K proj [b,h,s,dk-pair]
__device__ uint2 g_vt[(size_t)B_*H_*DK_*S_/2];  // V^T [b,h,dk,s-pair]
__device__ uint2 g_ap[(size_t)M_*D_/2];         // attn out [b*s][d-pair]

// ---------------- helpers -----------------------------------------------------
__device__ __forceinline__ uint32_t smem_to_u32(const void* p) {
    uint32_t a;
    asm("{ .reg .u64 t; cvta.to.shared.u64 t, %1; cvt.u32.u64 %0, t; }"
        : "=r"(a) : "l"(p));
    return a;
}
__device__ __forceinline__ void cp_async16(uint32_t dst, const void* src) {
    asm volatile("cp.async.ca.shared.global [%0], [%1], 16;" :: "r"(dst), "l"(src));
}
#define CP_COMMIT() asm volatile("cp.async.commit_group;" ::: "memory")
#define CP_WAIT(n)  asm volatile("cp.async.wait_group %0;" :: "n"(n) : "memory")

__device__ __forceinline__ uint2 pack_h2l2(float v0, float v1) {
    __half2 hp = __floats2half2_rn(v0, v1);
    const float l0 = v0 - __half2float(__low2half(hp));
    const float l1 = v1 - __half2float(__high2half(hp));
    __half2 lp = __floats2half2_rn(l0, l1);
    uint2 r;
    r.x = *reinterpret_cast<uint32_t*>(&hp);
    r.y = *reinterpret_cast<uint32_t*>(&lp);
    return r;
}

// D(16x8,f32) += A(16x16 f16 row) * B(16x8 f16 col)
__device__ __forceinline__ void mma_f16(float* d, const uint32_t* a, const uint32_t* b) {
    asm volatile("mma.sync.aligned.m16n8k16.row.col.f32.f16.f16.f32 "
        "{%0,%1,%2,%3}, {%4,%5,%6,%7}, {%8,%9}, {%0,%1,%2,%3};"
        : "+f"(d[0]), "+f"(d[1]), "+f"(d[2]), "+f"(d[3])
        : "r"(a[0]), "r"(a[1]), "r"(a[2]), "r"(a[3]), "r"(b[0]), "r"(b[1]));
}

// ---------------- prep: all 7 fp32 tensors -> h2l2 in ONE launch --------------
__global__ __launch_bounds__(256) void split_all(
    const float2* __restrict__ q,  const float2* __restrict__ k,
    const float2* __restrict__ v,  const float2* __restrict__ wq,
    const float2* __restrict__ wk, const float2* __restrict__ wv,
    const float2* __restrict__ wo)
{
    const int t = blockIdx.y;
    const size_t i = (size_t)blockIdx.x * 256 + threadIdx.x;
    const size_t n = (t < 3) ? (size_t)M_*D_/2 : (size_t)D_*D_/2;
    if (i >= n) return;
    const float2* src;
    uint2* dst;
    switch (t) {
        case 0:  src = q;  dst = g_qi; break;
        case 1:  src = k;  dst = g_ki; break;
        case 2:  src = v;  dst = g_vi; break;
        case 3:  src = wq; dst = g_wq; break;
        case 4:  src = wk; dst = g_wk; break;
        case 5:  src = wv; dst = g_wv; break;
        default: src = wo; dst = g_wo; break;
    }
    const float2 x = src[i];
    dst[i] = pack_h2l2(x.x, x.y);
}

// ---------------- 3xFP16 GEMM mainloop (shared by QKV + O) -------------------
#define PSTR 20                       // pairs per smem row (16 + 4 pad)
#define GSM_STAGE (128*PSTR)          // uint2 per stage
#define GEMM_SMEM (4*GSM_STAGE*8)     // A2 + B2 stages = 81920 B

__device__ __forceinline__ void gemm_mainloop(
    const uint2* __restrict__ Ag, const uint2* __restrict__ Wg,
    uint2* As, uint2* Bs, uint32_t sA, uint32_t sB,
    int m0, int n0, int tid, int wm, int wn, int g, int c,
    float acc[2][8][4])
{
    #define G_LOAD(st, chk) do { \
        _Pragma("unroll") \
        for (int i = 0; i < 4; i++) { \
            const int idx = tid + i*256, row = idx >> 3, ch = idx & 7; \
            cp_async16(sA + (uint32_t)((((st)*128+row)*PSTR + ch*2)*8), \
                       Ag + (size_t)(m0+row)*512 + (chk)*16 + ch*2); \
            cp_async16(sB + (uint32_t)((((st)*128+row)*PSTR + ch*2)*8), \
                       Wg + (size_t)(n0+row)*512 + (chk)*16 + ch*2); \
        } \
    } while (0)

    G_LOAD(0, 0); CP_COMMIT();

    for (int chk = 0; chk < 32; chk++) {
        const int st = chk & 1;
        if (chk < 31) { G_LOAD(st^1, chk+1); CP_COMMIT(); CP_WAIT(1); }
        else CP_WAIT(0);
        __syncthreads();

        const uint2* Ast = As + st*GSM_STAGE;
        const uint2* Bst = Bs + st*GSM_STAGE;
        #pragma unroll
        for (int ks = 0; ks < 2; ks++) {
            const int p0 = ks*8 + c, p1 = p0 + 4;
            uint32_t ah[2][4], al[2][4];
            #pragma unroll
            for (int mt = 0; mt < 2; mt++) {
                const uint2 a0 = Ast[(wm+mt*16+g  )*PSTR + p0];
                const uint2 a1 = Ast[(wm+mt*16+g+8)*PSTR + p0];
                const uint2 a2 = Ast[(wm+mt*16+g  )*PSTR + p1];
                const uint2 a3 = Ast[(wm+mt*16+g+8)*PSTR + p1];
                ah[mt][0]=a0.x; ah[mt][1]=a1.x; ah[mt][2]=a2.x; ah[mt][3]=a3.x;
                al[mt][0]=a0.y; al[mt][1]=a1.y; al[mt][2]=a2.y; al[mt][3]=a3.y;
            }
            #pragma unroll
            for (int nt = 0; nt < 8; nt++) {
                const uint2 b0 = Bst[(wn+nt*8+g)*PSTR + p0];
                const uint2 b1 = Bst[(wn+nt*8+g)*PSTR + p1];
                uint32_t bh[2] = {b0.x, b1.x};
                uint32_t bl[2] = {b0.y, b1.y};
                #pragma unroll
                for (int mt = 0; mt < 2; mt++) {
                    mma_f16(acc[mt][nt], ah[mt], bh);
                    mma_f16(acc[mt][nt], ah[mt], bl);
                    mma_f16(acc[mt][nt], al[mt], bh);
                }
            }
        }
        __syncthreads();
    }
    #undef G_LOAD
}

// ---------------- merged Q/K/V projection GEMM (one launch, z selects) --------
// z=0: Q -> g_qp pairs.  z=1: K -> g_kp pairs.  z=2: V -> g_vt transposed pairs.
__global__ __launch_bounds__(256, 2) void gemm_qkv(
    const float* __restrict__ bq, const float* __restrict__ bk,
    const float* __restrict__ bv)
{
    extern __shared__ uint2 smu[];
    uint2* As = smu;
    uint2* Bs = smu + 2*GSM_STAGE;
    const int tid = threadIdx.x, lane = tid & 31, wid = tid >> 5;
    const int g = lane >> 2, c = lane & 3;
    const int wm = (wid & 3)*32, wn = (wid >> 2)*64;
    const int m0 = blockIdx.x*128, n0 = blockIdx.y*128;
    const int z = blockIdx.z;
    const uint32_t sA = smem_to_u32(As), sB = smem_to_u32(Bs);

    const uint2* Ag = (z == 0) ? g_qi : (z == 1) ? g_ki : g_vi;
    const uint2* Wg = (z == 0) ? g_wq : (z == 1) ? g_wk : g_wv;
    const float* bias = (z == 0) ? bq : (z == 1) ? bk : bv;

    float acc[2][8][4] = {};
    gemm_mainloop(Ag, Wg, As, Bs, sA, sB, m0, n0, tid, wm, wn, g, c, acc);

    if (z < 2) {
        uint2* Cp = (z == 0) ? g_qp : g_kp;
        #pragma unroll
        for (int mt = 0; mt < 2; mt++)
          #pragma unroll
          for (int hf = 0; hf < 2; hf++) {
            const int m = m0 + wm + mt*16 + g + hf*8;
            #pragma unroll
            for (int nt = 0; nt < 8; nt++) {
                const int n = n0 + wn + nt*8 + c*2;
                const float v0 = acc[mt][nt][hf*2+0] + bias[n];
                const float v1 = acc[mt][nt][hf*2+1] + bias[n+1];
                const int bb = m >> 11, ss = m & (S_-1);
                const int hh = n >> 6,  dk = n & 63;
                Cp[(((size_t)bb*H_ + hh)*S_ + ss)*32 + (dk >> 1)] = pack_h2l2(v0, v1);
            }
          }
    } else {
        // V: transpose in smem (reuse cp.async buffers), write h2l2 to g_vt
        float* tile = (float*)smu;   // [128 n][132]
        #pragma unroll
        for (int mt = 0; mt < 2; mt++)
          #pragma unroll
          for (int hf = 0; hf < 2; hf++) {
            const int ml = wm + mt*16 + g + hf*8;
            #pragma unroll
            for (int nt = 0; nt < 8; nt++) {
                const int nl = wn + nt*8 + c*2;
                tile[(nl  )*132 + ml] = acc[mt][nt][hf*2+0] + bias[n0+nl];
                tile[(nl+1)*132 + ml] = acc[mt][nt][hf*2+1] + bias[n0+nl+1];
            }
          }
        __syncthreads();
        const int bb = m0 >> 11, sp0 = (m0 & (S_-1)) >> 1;
        #pragma unroll
        for (int i = 0; i < 32; i++) {
            const int idx = tid + i*256;      // 0..8191
            const int nl = idx >> 6;          // 0..127
            const int sp = idx & 63;          // 0..63
            const int hh = (n0 + nl) >> 6, dk = (n0 + nl) & 63;
            const float v0 = tile[nl*132 + 2*sp];
            const float v1 = tile[nl*132 + 2*sp + 1];
            g_vt[(((size_t)bb*H_ + hh)*DK_ + dk)*(S_/2) + sp0 + sp] = pack_h2l2(v0, v1);
        }
    }
}

// ---------------- output GEMM: out = Ap @ Wo^T + bias -------------------------
__global__ __launch_bounds__(256, 2) void gemm_out(const float* __restrict__ bias,
                                                   float* __restrict__ C)
{
    extern __shared__ uint2 smu[];
    uint2* As = smu;
    uint2* Bs = smu + 2*GSM_STAGE;
    const int tid = threadIdx.x, lane = tid & 31, wid = tid >> 5;
    const int g = lane >> 2, c = lane & 3;
    const int wm = (wid & 3)*32, wn = (wid >> 2)*64;
    const int m0 = blockIdx.x*128, n0 = blockIdx.y*128;
    const uint32_t sA = smem_to_u32(As), sB = smem_to_u32(Bs);

    float acc[2][8][4] = {};
    gemm_mainloop(g_ap, g_wo, As, Bs, sA, sB, m0, n0, tid, wm, wn, g, c, acc);

    #pragma unroll
    for (int mt = 0; mt < 2; mt++)
      #pragma unroll
      for (int hf = 0; hf < 2; hf++) {
        const int m = m0 + wm + mt*16 + g + hf*8;
        #pragma unroll
        for (int nt = 0; nt < 8; nt++) {
            const int n = n0 + wn + nt*8 + c*2;
            *(float2*)(C + (size_t)m*D_ + n) =
                make_float2(acc[mt][nt][hf*2+0] + bias[n],
                            acc[mt][nt][hf*2+1] + bias[n+1]);
        }
      }
}

// ---------------- fp16 flash attention ----------------------------------------
// 256 thr, 8 warps x 16 q-rows, q-tile 128, k-tile 64, 2-stage K/V cp.async.
#define ASTR 36                       // pairs per smem row (32 + 4 pad)
#define ATTN_SMEM ((128*ASTR + 4*64*ASTR)*8)   // 110592 B

__global__ __launch_bounds__(256, 2) void attn_f16()
{
    extern __shared__ uint2 smu[];
    uint2* Qp = smu;                      // [128][ASTR]
    uint2* Kp = smu + 128*ASTR;           // [2][64][ASTR]
    uint2* Vp = Kp + 2*64*ASTR;           // [2][64][ASTR]
    const int tid = threadIdx.x, lane = tid & 31, wid = tid >> 5;
    const int g = lane >> 2, c = lane & 3;
    const int wr = wid * 16;
    const int h = blockIdx.y, b = blockIdx.z;
    const int q0 = blockIdx.x * 128;
    const size_t bh = (size_t)b*H_ + h;
    const uint2* qg  = g_qp + (bh*S_ + q0)*32;
    const uint2* kg  = g_kp + bh*S_*32;
    const uint2* vtg = g_vt + bh*DK_*(S_/2);
    const uint32_t sQ = smem_to_u32(Qp), sK = smem_to_u32(Kp), sV = smem_to_u32(Vp);

    #pragma unroll
    for (int i = 0; i < 8; i++) {
        const int idx = tid + i*256;
        const int row = idx >> 4, ch = idx & 15;
        cp_async16(sQ + (uint32_t)((row*ASTR + ch*2)*8), qg + (size_t)row*32 + ch*2);
    }
    #pragma unroll
    for (int i = 0; i < 4; i++) {
        const int idx = tid + i*256;
        const int row = idx >> 4, ch = idx & 15;
        cp_async16(sK + (uint32_t)((row*ASTR + ch*2)*8), kg + (size_t)row*32 + ch*2);
        cp_async16(sV + (uint32_t)((row*ASTR + ch*2)*8), vtg + (size_t)row*(S_/2) + ch*2);
    }
    CP_COMMIT();

    float o[8][4] = {};
    float mrun[2] = {-1e30f, -1e30f};
    float lrun[2] = {0.f, 0.f};

    for (int t = 0; t < S_/64; t++) {
        const int st = t & 1;
        if (t < S_/64 - 1) {
            const int s2 = st ^ 1;
            #pragma unroll
            for (int i = 0; i < 4; i++) {
                const int idx = tid + i*256;
                const int row = idx >> 4, ch = idx & 15;
                cp_async16(sK + (uint32_t)((((s2*64)+row)*ASTR + ch*2)*8),
                           kg + (size_t)((t+1)*64 + row)*32 + ch*2);
                cp_async16(sV + (uint32_t)((((s2*64)+row)*ASTR + ch*2)*8),
                           vtg + (size_t)row*(S_/2) + (t+1)*32 + ch*2);
            }
            CP_COMMIT(); CP_WAIT(1);
        } else {
            CP_WAIT(0);
        }
        __syncthreads();

        const uint2* Kst = Kp + st*64*ASTR;
        const uint2* Vst = Vp + st*64*ASTR;

        // ---- S = (Q K^T)/8 --------------------------------------------------
        float s[8][4] = {};
        #pragma unroll
        for (int ks = 0; ks < 4; ks++) {
            const int p0 = ks*8 + c, p1 = p0 + 4;
            const uint2 a0 = Qp[(wr+g  )*ASTR + p0];
            const uint2 a1 = Qp[(wr+g+8)*ASTR + p0];
            const uint2 a2 = Qp[(wr+g  )*ASTR + p1];
            const uint2 a3 = Qp[(wr+g+8)*ASTR + p1];
            uint32_t ah[4] = {a0.x, a1.x, a2.x, a3.x};
            uint32_t al[4] = {a0.y, a1.y, a2.y, a3.y};
            #pragma unroll
            for (int nt = 0; nt < 8; nt++) {
                const uint2 b0 = Kst[(nt*8+g)*ASTR + p0];
                const uint2 b1 = Kst[(nt*8+g)*ASTR + p1];
                uint32_t bh2[2] = {b0.x, b1.x};
                uint32_t bl2[2] = {b0.y, b1.y};
                mma_f16(s[nt], ah, bh2);
                mma_f16(s[nt], ah, bl2);
                mma_f16(s[nt], al, bh2);
            }
        }

        // ---- online softmax (rows g, g+8; stats across 4 c-lanes) -----------
        #pragma unroll
        for (int hf = 0; hf < 2; hf++) {
            float mx = -1e30f;
            #pragma unroll
            for (int nt = 0; nt < 8; nt++) {
                s[nt][hf*2]   *= 0.125f;
                s[nt][hf*2+1] *= 0.125f;
                mx = fmaxf(mx, fmaxf(s[nt][hf*2], s[nt][hf*2+1]));
            }
            mx = fmaxf(mx, __shfl_xor_sync(0xffffffffu, mx, 1));
            mx = fmaxf(mx, __shfl_xor_sync(0xffffffffu, mx, 2));
            const float mn = fmaxf(mrun[hf], mx);
            const float corr = __expf(mrun[hf] - mn);
            mrun[hf] = mn;
            float ls = 0.f;
            #pragma unroll
            for (int nt = 0; nt < 8; nt++) {
                const float e0 = __expf(s[nt][hf*2]   - mn);
                const float e1 = __expf(s[nt][hf*2+1] - mn);
                s[nt][hf*2] = e0; s[nt][hf*2+1] = e1;
                ls += e0 + e1;
            }
            ls += __shfl_xor_sync(0xffffffffu, ls, 1);
            ls += __shfl_xor_sync(0xffffffffu, ls, 2);
            lrun[hf] = lrun[hf]*corr + ls;
            #pragma unroll
            for (int nt = 0; nt < 8; nt++) {
                o[nt][hf*2]   *= corr;
                o[nt][hf*2+1] *= corr;
            }
        }

        // ---- P fragments directly from acc registers ------------------------
        uint32_t pa[4][4];
        #pragma unroll
        for (int kv = 0; kv < 4; kv++) {
            __half2 h0 = __floats2half2_rn(s[2*kv  ][0], s[2*kv  ][1]);
            __half2 h1 = __floats2half2_rn(s[2*kv  ][2], s[2*kv  ][3]);
            __half2 h2 = __floats2half2_rn(s[2*kv+1][0], s[2*kv+1][1]);
            __half2 h3 = __floats2half2_rn(s[2*kv+1][2], s[2*kv+1][3]);
            pa[kv][0] = *reinterpret_cast<uint32_t*>(&h0);
            pa[kv][1] = *reinterpret_cast<uint32_t*>(&h1);
            pa[kv][2] = *reinterpret_cast<uint32_t*>(&h2);
            pa[kv][3] = *reinterpret_cast<uint32_t*>(&h3);
        }

        // ---- O += P V (V 2-term) --------------------------------------------
        #pragma unroll
        for (int kv = 0; kv < 4; kv++) {
            const int p0 = kv*8 + c, p1 = p0 + 4;
            #pragma unroll
            for (int nt = 0; nt < 8; nt++) {
                const uint2 v0 = Vst[(nt*8+g)*ASTR + p0];
                const uint2 v1 = Vst[(nt*8+g)*ASTR + p1];
                uint32_t vh2[2] = {v0.x, v1.x};
                uint32_t vl2[2] = {v0.y, v1.y};
                mma_f16(o[nt], pa[kv], vh2);
                mma_f16(o[nt], pa[kv], vl2);
            }
        }
        __syncthreads();
    }

    // epilogue: normalize, split, store h2l2 pairs for the O-GEMM
    #pragma unroll
    for (int hf = 0; hf < 2; hf++) {
        const int r = q0 + wr + g + hf*8;
        const float inv = 1.f / lrun[hf];
        #pragma unroll
        for (int nt = 0; nt < 8; nt++) {
            const int pairidx = h*32 + nt*4 + c;
            g_ap[((size_t)b*S_ + r)*512 + pairidx] =
                pack_h2l2(o[nt][hf*2]*inv, o[nt][hf*2+1]*inv);
        }
    }
}

// ---------------- launch ------------------------------------------------------
extern "C" void kernel_launch(void* const* d_in, const int* in_sizes, int n_in,
                              void* d_out, int out_size)
{
    (void)in_sizes; (void)n_in; (void)out_size;
    const float* Q  = (const float*)d_in[0];
    const float* K  = (const float*)d_in[1];
    const float* V  = (const float*)d_in[2];
    const float* bq = (const float*)d_in[4];
    const float* bk = (const float*)d_in[6];
    const float* bv = (const float*)d_in[8];
    const float* bo = (const float*)d_in[10];
    const float* Wq = (const float*)d_in[3];
    const float* Wk = (const float*)d_in[5];
    const float* Wv = (const float*)d_in[7];
    const float* Wo = (const float*)d_in[9];
    float* out = (float*)d_out;

    cudaFuncSetAttribute(gemm_qkv, cudaFuncAttributeMaxDynamicSharedMemorySize, GEMM_SMEM);
    cudaFuncSetAttribute(gemm_out, cudaFuncAttributeMaxDynamicSharedMemorySize, GEMM_SMEM);
    cudaFuncSetAttribute(attn_f16, cudaFuncAttributeMaxDynamicSharedMemorySize, ATTN_SMEM);

    // one prep launch: inputs (y=0..2, 2M pairs) + weights (y=3..6, 512K pairs)
    split_all<<<dim3(8192, 7), 256>>>((const float2*)Q,  (const float2*)K,
                                      (const float2*)V,  (const float2*)Wq,
                                      (const float2*)Wk, (const float2*)Wv,
                                      (const float2*)Wo);

    // one merged QKV projection launch (z: 0=Q, 1=K, 2=V+transpose)
    gemm_qkv<<<dim3(M_/128, D_/128, 3), 256, GEMM_SMEM>>>(bq, bk, bv);

    attn_f16<<<dim3(S_/128, H_, B_), 256, ATTN_SMEM>>>();

    gemm_out<<<dim3(M_/128, D_/128), 256, GEMM_SMEM>>>(bo, out);
}

// round 7
// speedup vs baseline: 2.2211x; 1.2028x over previous
#include <cuda_runtime.h>
#include <cuda_fp16.h>
#include <math.h>
#include <stdint.h>

#define B_  2
#define S_  2048
#define D_  1024
#define H_  16
#define DK_ 64
#define M_  (B_*S_)   // 4096

// ---------------- scratch: separate hi/lo fp16 planes -------------------------
__device__ __half g_qih[(size_t)M_*D_]; __device__ __half g_qil[(size_t)M_*D_];
__device__ __half g_kih[(size_t)M_*D_]; __device__ __half g_kil[(size_t)M_*D_];
__device__ __half g_vih[(size_t)M_*D_]; __device__ __half g_vil[(size_t)M_*D_];
__device__ __half g_wqh[(size_t)D_*D_]; __device__ __half g_wql[(size_t)D_*D_];
__device__ __half g_wkh[(size_t)D_*D_]; __device__ __half g_wkl[(size_t)D_*D_];
__device__ __half g_wvh[(size_t)D_*D_]; __device__ __half g_wvl[(size_t)D_*D_];
__device__ __half g_woh[(size_t)D_*D_]; __device__ __half g_wol[(size_t)D_*D_];
__device__ __half g_qph[(size_t)B_*H_*S_*DK_]; __device__ __half g_qpl[(size_t)B_*H_*S_*DK_];
__device__ __half g_kph[(size_t)B_*H_*S_*DK_]; __device__ __half g_kpl[(size_t)B_*H_*S_*DK_];
__device__ __half g_vth[(size_t)B_*H_*DK_*S_]; __device__ __half g_vtl[(size_t)B_*H_*DK_*S_];
__device__ __half g_aph[(size_t)M_*D_]; __device__ __half g_apl[(size_t)M_*D_];

// ---------------- helpers -----------------------------------------------------
__device__ __forceinline__ uint32_t smem_to_u32(const void* p) {
    uint32_t a;
    asm("{ .reg .u64 t; cvta.to.shared.u64 t, %1; cvt.u32.u64 %0, t; }"
        : "=r"(a) : "l"(p));
    return a;
}
__device__ __forceinline__ void cp_async16(uint32_t dst, const void* src) {
    asm volatile("cp.async.ca.shared.global [%0], [%1], 16;" :: "r"(dst), "l"(src));
}
#define CP_COMMIT() asm volatile("cp.async.commit_group;" ::: "memory")
#define CP_WAIT(n)  asm volatile("cp.async.wait_group %0;" :: "n"(n) : "memory")

#define LDSM4(r0,r1,r2,r3,addr) \
    asm volatile("ldmatrix.sync.aligned.m8n8.x4.shared.b16 {%0,%1,%2,%3}, [%4];" \
        : "=r"(r0),"=r"(r1),"=r"(r2),"=r"(r3) : "r"(addr))

__device__ __forceinline__ void split2(float x, float y, uint32_t& h2, uint32_t& l2) {
    __half2 hp = __floats2half2_rn(x, y);
    const float lx = x - __half2float(__low2half(hp));
    const float ly = y - __half2float(__high2half(hp));
    __half2 lp = __floats2half2_rn(lx, ly);
    h2 = *reinterpret_cast<uint32_t*>(&hp);
    l2 = *reinterpret_cast<uint32_t*>(&lp);
}

__device__ __forceinline__ void mma_f16(float* d, const uint32_t* a, const uint32_t* b) {
    asm volatile("mma.sync.aligned.m16n8k16.row.col.f32.f16.f16.f32 "
        "{%0,%1,%2,%3}, {%4,%5,%6,%7}, {%8,%9}, {%0,%1,%2,%3};"
        : "+f"(d[0]), "+f"(d[1]), "+f"(d[2]), "+f"(d[3])
        : "r"(a[0]), "r"(a[1]), "r"(a[2]), "r"(a[3]), "r"(b[0]), "r"(b[1]));
}

// ---------------- prep: 7 fp32 tensors -> hi/lo planes, one launch ------------
__global__ __launch_bounds__(256) void split_all(
    const float4* __restrict__ q,  const float4* __restrict__ k,
    const float4* __restrict__ v,  const float4* __restrict__ wq,
    const float4* __restrict__ wk, const float4* __restrict__ wv,
    const float4* __restrict__ wo)
{
    const int t = blockIdx.y;
    const size_t i = (size_t)blockIdx.x * 256 + threadIdx.x;   // per float4
    const size_t n = (t < 3) ? (size_t)M_*D_/4 : (size_t)D_*D_/4;
    if (i >= n) return;
    const float4* src; __half *dh, *dl;
    switch (t) {
        case 0:  src = q;  dh = g_qih; dl = g_qil; break;
        case 1:  src = k;  dh = g_kih; dl = g_kil; break;
        case 2:  src = v;  dh = g_vih; dl = g_vil; break;
        case 3:  src = wq; dh = g_wqh; dl = g_wql; break;
        case 4:  src = wk; dh = g_wkh; dl = g_wkl; break;
        case 5:  src = wv; dh = g_wvh; dl = g_wvl; break;
        default: src = wo; dh = g_woh; dl = g_wol; break;
    }
    const float4 x = src[i];
    uint32_t h0, l0, h1, l1;
    split2(x.x, x.y, h0, l0);
    split2(x.z, x.w, h1, l1);
    ((uint2*)dh)[i] = make_uint2(h0, h1);
    ((uint2*)dl)[i] = make_uint2(l0, l1);
}

// ---------------- 3xFP16 GEMM mainloop (ldmatrix) -----------------------------
#define AST 40                          // halves per smem row (32 + 8 pad)
#define PLANE (128*AST)                 // halves per stage-plane
#define GEMM_SMEM (8*PLANE*2)           // 4 planes x 2 stages = 81920 B

__device__ __forceinline__ void gemm_mainloop(
    const __half* __restrict__ Agh, const __half* __restrict__ Agl,
    const __half* __restrict__ Wgh, const __half* __restrict__ Wgl,
    uint32_t sAh, uint32_t sAl, uint32_t sBh, uint32_t sBl,
    int m0, int n0, int tid, int wm, int wn, int lane,
    float acc[2][8][4])
{
    const int lr = lane & 7;
    const int a_ro = lr + ((lane >> 3) & 1) * 8;   // A ldmatrix row offset
    const int a_co = ((lane >> 4) & 1) * 8;        // A col offset
    const int b_ro = lr + ((lane >> 4) & 1) * 8;   // B row offset
    const int b_co = ((lane >> 3) & 1) * 8;        // B col offset

    #define G_LOAD(st, chk) do { \
        _Pragma("unroll") \
        for (int i = 0; i < 2; i++) { \
            const int idx = tid + i*256, row = idx >> 2, seg = idx & 3; \
            const uint32_t so = (uint32_t)((((st)*128+row)*AST + seg*8)*2); \
            cp_async16(sAh + so, Agh + (size_t)(m0+row)*1024 + (chk)*32 + seg*8); \
            cp_async16(sAl + so, Agl + (size_t)(m0+row)*1024 + (chk)*32 + seg*8); \
            cp_async16(sBh + so, Wgh + (size_t)(n0+row)*1024 + (chk)*32 + seg*8); \
            cp_async16(sBl + so, Wgl + (size_t)(n0+row)*1024 + (chk)*32 + seg*8); \
        } \
    } while (0)

    G_LOAD(0, 0); CP_COMMIT();

    for (int chk = 0; chk < 32; chk++) {
        const int st = chk & 1;
        if (chk < 31) { G_LOAD(st^1, chk+1); CP_COMMIT(); CP_WAIT(1); }
        else CP_WAIT(0);
        __syncthreads();

        const uint32_t stoff = (uint32_t)(st*PLANE*2);
        #pragma unroll
        for (int ks = 0; ks < 2; ks++) {
            uint32_t ah[2][4], al[2][4];
            #pragma unroll
            for (int mt = 0; mt < 2; mt++) {
                const uint32_t ao = stoff +
                    (uint32_t)(((wm + mt*16 + a_ro)*AST + ks*16 + a_co)*2);
                LDSM4(ah[mt][0], ah[mt][1], ah[mt][2], ah[mt][3], sAh + ao);
                LDSM4(al[mt][0], al[mt][1], al[mt][2], al[mt][3], sAl + ao);
            }
            #pragma unroll
            for (int np = 0; np < 4; np++) {
                const uint32_t bo = stoff +
                    (uint32_t)(((wn + np*16 + b_ro)*AST + ks*16 + b_co)*2);
                uint32_t b0h, b1h, b2h, b3h, b0l, b1l, b2l, b3l;
                LDSM4(b0h, b1h, b2h, b3h, sBh + bo);
                LDSM4(b0l, b1l, b2l, b3l, sBl + bo);
                uint32_t bhA[2] = {b0h, b1h}, bhB[2] = {b2h, b3h};
                uint32_t blA[2] = {b0l, b1l}, blB[2] = {b2l, b3l};
                #pragma unroll
                for (int mt = 0; mt < 2; mt++) {
                    mma_f16(acc[mt][2*np  ], ah[mt], bhA);
                    mma_f16(acc[mt][2*np  ], ah[mt], blA);
                    mma_f16(acc[mt][2*np  ], al[mt], bhA);
                    mma_f16(acc[mt][2*np+1], ah[mt], bhB);
                    mma_f16(acc[mt][2*np+1], ah[mt], blB);
                    mma_f16(acc[mt][2*np+1], al[mt], bhB);
                }
            }
        }
        __syncthreads();
    }
    #undef G_LOAD
}

// ---------------- merged Q/K/V projection GEMM --------------------------------
__global__ __launch_bounds__(256, 2) void gemm_qkv(
    const float* __restrict__ bq, const float* __restrict__ bk,
    const float* __restrict__ bv)
{
    extern __shared__ __half smh[];
    const uint32_t base = smem_to_u32(smh);
    const uint32_t sAh = base, sAl = base + 2*PLANE*2;
    const uint32_t sBh = base + 4*PLANE*2, sBl = base + 6*PLANE*2;
    const int tid = threadIdx.x, lane = tid & 31, wid = tid >> 5;
    const int g = lane >> 2, c = lane & 3;
    const int wm = (wid & 3)*32, wn = (wid >> 2)*64;
    const int m0 = blockIdx.x*128, n0 = blockIdx.y*128;
    const int z = blockIdx.z;

    const __half *Agh, *Agl, *Wgh, *Wgl;
    const float* bias;
    if (z == 0) { Agh=g_qih; Agl=g_qil; Wgh=g_wqh; Wgl=g_wql; bias=bq; }
    else if (z == 1) { Agh=g_kih; Agl=g_kil; Wgh=g_wkh; Wgl=g_wkl; bias=bk; }
    else { Agh=g_vih; Agl=g_vil; Wgh=g_wvh; Wgl=g_wvl; bias=bv; }

    float acc[2][8][4] = {};
    gemm_mainloop(Agh, Agl, Wgh, Wgl, sAh, sAl, sBh, sBl,
                  m0, n0, tid, wm, wn, lane, acc);

    if (z < 2) {
        __half* Ch = (z == 0) ? g_qph : g_kph;
        __half* Cl = (z == 0) ? g_qpl : g_kpl;
        #pragma unroll
        for (int mt = 0; mt < 2; mt++)
          #pragma unroll
          for (int hf = 0; hf < 2; hf++) {
            const int m = m0 + wm + mt*16 + g + hf*8;
            const int bb = m >> 11, ss = m & (S_-1);
            #pragma unroll
            for (int nt = 0; nt < 8; nt++) {
                const int n = n0 + wn + nt*8 + c*2;
                const int hh = n >> 6, dk = n & 63;
                uint32_t h2, l2;
                split2(acc[mt][nt][hf*2+0] + bias[n],
                       acc[mt][nt][hf*2+1] + bias[n+1], h2, l2);
                const size_t o = ((((size_t)bb*H_ + hh)*S_ + ss)*DK_ + dk) >> 1;
                ((uint32_t*)Ch)[o] = h2;
                ((uint32_t*)Cl)[o] = l2;
            }
          }
    } else {
        // V: transpose through smem (reuse staging buffers), write V^T planes
        float* tile = (float*)smh;   // [128 n][132]
        __syncthreads();
        #pragma unroll
        for (int mt = 0; mt < 2; mt++)
          #pragma unroll
          for (int hf = 0; hf < 2; hf++) {
            const int ml = wm + mt*16 + g + hf*8;
            #pragma unroll
            for (int nt = 0; nt < 8; nt++) {
                const int nl = wn + nt*8 + c*2;
                tile[(nl  )*132 + ml] = acc[mt][nt][hf*2+0] + bias[n0+nl];
                tile[(nl+1)*132 + ml] = acc[mt][nt][hf*2+1] + bias[n0+nl+1];
            }
          }
        __syncthreads();
        const int bb = m0 >> 11, s0 = m0 & (S_-1);
        #pragma unroll
        for (int i = 0; i < 32; i++) {
            const int idx = tid + i*256;      // 0..8191
            const int nl = idx >> 6;          // 0..127
            const int sp = idx & 63;          // 0..63 (s-pair)
            const int hh = (n0 + nl) >> 6, dk = (n0 + nl) & 63;
            uint32_t h2, l2;
            split2(tile[nl*132 + 2*sp], tile[nl*132 + 2*sp + 1], h2, l2);
            const size_t o = ((((size_t)bb*H_ + hh)*DK_ + dk)*S_ + s0 + 2*sp) >> 1;
            ((uint32_t*)g_vth)[o] = h2;
            ((uint32_t*)g_vtl)[o] = l2;
        }
    }
}

// ---------------- output GEMM -------------------------------------------------
__global__ __launch_bounds__(256, 2) void gemm_out(const float* __restrict__ bias,
                                                   float* __restrict__ C)
{
    extern __shared__ __half smh[];
    const uint32_t base = smem_to_u32(smh);
    const uint32_t sAh = base, sAl = base + 2*PLANE*2;
    const uint32_t sBh = base + 4*PLANE*2, sBl = base + 6*PLANE*2;
    const int tid = threadIdx.x, lane = tid & 31, wid = tid >> 5;
    const int g = lane >> 2, c = lane & 3;
    const int wm = (wid & 3)*32, wn = (wid >> 2)*64;
    const int m0 = blockIdx.x*128, n0 = blockIdx.y*128;

    float acc[2][8][4] = {};
    gemm_mainloop(g_aph, g_apl, g_woh, g_wol, sAh, sAl, sBh, sBl,
                  m0, n0, tid, wm, wn, lane, acc);

    #pragma unroll
    for (int mt = 0; mt < 2; mt++)
      #pragma unroll
      for (int hf = 0; hf < 2; hf++) {
        const int m = m0 + wm + mt*16 + g + hf*8;
        #pragma unroll
        for (int nt = 0; nt < 8; nt++) {
            const int n = n0 + wn + nt*8 + c*2;
            *(float2*)(C + (size_t)m*D_ + n) =
                make_float2(acc[mt][nt][hf*2+0] + bias[n],
                            acc[mt][nt][hf*2+1] + bias[n+1]);
        }
      }
}

// ---------------- fp16 flash attention (ldmatrix) -----------------------------
#define TST 72                          // halves per smem row (64 + 8 pad)
// Qh/Ql [128][72], Kh/Kl [2][64][72], Vh/Vl [2][64][72]
#define SM_QH 0
#define SM_QL (128*TST)
#define SM_KH (2*128*TST)
#define SM_KL (SM_KH + 2*64*TST)
#define SM_VH (SM_KL + 2*64*TST)
#define SM_VL (SM_VH + 2*64*TST)
#define ATTN_SMEM ((SM_VL + 2*64*TST)*2)   // 110592 B

__global__ __launch_bounds__(256, 2) void attn_f16()
{
    extern __shared__ __half smh[];
    const uint32_t base = smem_to_u32(smh);
    const int tid = threadIdx.x, lane = tid & 31, wid = tid >> 5;
    const int g = lane >> 2, c = lane & 3;
    const int wr = wid * 16;
    const int h = blockIdx.y, b = blockIdx.z;
    const int q0 = blockIdx.x * 128;
    const size_t bh = (size_t)b*H_ + h;
    const __half* qgh = g_qph + (bh*S_ + q0)*DK_;
    const __half* qgl = g_qpl + (bh*S_ + q0)*DK_;
    const __half* kgh = g_kph + bh*S_*DK_;
    const __half* kgl = g_kpl + bh*S_*DK_;
    const __half* vgh = g_vth + bh*DK_*S_;
    const __half* vgl = g_vtl + bh*DK_*S_;

    const int lr = lane & 7;
    const int a_ro = lr + ((lane >> 3) & 1) * 8;
    const int a_co = ((lane >> 4) & 1) * 8;
    const int b_ro = lr + ((lane >> 4) & 1) * 8;
    const int b_co = ((lane >> 3) & 1) * 8;

    // prologue: Q planes + K/V tile 0
    #pragma unroll
    for (int i = 0; i < 4; i++) {
        const int idx = tid + i*256;          // 0..1023
        const int row = idx >> 3, seg = idx & 7;
        const uint32_t so = (uint32_t)((row*TST + seg*8)*2);
        cp_async16(base + SM_QH*2 + so, qgh + (size_t)row*DK_ + seg*8);
        cp_async16(base + SM_QL*2 + so, qgl + (size_t)row*DK_ + seg*8);
    }
    #pragma unroll
    for (int i = 0; i < 2; i++) {
        const int idx = tid + i*256;          // 0..511
        const int row = idx >> 3, seg = idx & 7;
        const uint32_t so = (uint32_t)((row*TST + seg*8)*2);
        cp_async16(base + SM_KH*2 + so, kgh + (size_t)row*DK_ + seg*8);
        cp_async16(base + SM_KL*2 + so, kgl + (size_t)row*DK_ + seg*8);
        cp_async16(base + SM_VH*2 + so, vgh + (size_t)row*S_ + seg*8);
        cp_async16(base + SM_VL*2 + so, vgl + (size_t)row*S_ + seg*8);
    }
    CP_COMMIT();

    float o[8][4] = {};
    float mrun[2] = {-1e30f, -1e30f};
    float lrun[2] = {0.f, 0.f};

    for (int t = 0; t < S_/64; t++) {
        const int st = t & 1;
        if (t < S_/64 - 1) {
            const int s2 = st ^ 1;
            #pragma unroll
            for (int i = 0; i < 2; i++) {
                const int idx = tid + i*256;
                const int row = idx >> 3, seg = idx & 7;
                const uint32_t so = (uint32_t)(((s2*64 + row)*TST + seg*8)*2);
                cp_async16(base + SM_KH*2 + so, kgh + (size_t)((t+1)*64+row)*DK_ + seg*8);
                cp_async16(base + SM_KL*2 + so, kgl + (size_t)((t+1)*64+row)*DK_ + seg*8);
                cp_async16(base + SM_VH*2 + so, vgh + (size_t)row*S_ + (t+1)*64 + seg*8);
                cp_async16(base + SM_VL*2 + so, vgl + (size_t)row*S_ + (t+1)*64 + seg*8);
            }
            CP_COMMIT(); CP_WAIT(1);
        } else {
            CP_WAIT(0);
        }
        __syncthreads();

        const uint32_t kst = (uint32_t)((SM_KH + st*64*TST)*2);
        const uint32_t lst = (uint32_t)((SM_KL + st*64*TST)*2);
        const uint32_t vhst = (uint32_t)((SM_VH + st*64*TST)*2);
        const uint32_t vlst = (uint32_t)((SM_VL + st*64*TST)*2);

        // ---- S = (Q K^T)/8 --------------------------------------------------
        float s[8][4] = {};
        #pragma unroll
        for (int ks = 0; ks < 4; ks++) {
            const uint32_t qo = (uint32_t)(((wr + a_ro)*TST + ks*16 + a_co)*2);
            uint32_t ah[4], al[4];
            LDSM4(ah[0], ah[1], ah[2], ah[3], base + SM_QH*2 + qo);
            LDSM4(al[0], al[1], al[2], al[3], base + SM_QL*2 + qo);
            #pragma unroll
            for (int np = 0; np < 4; np++) {
                const uint32_t ko = (uint32_t)(((np*16 + b_ro)*TST + ks*16 + b_co)*2);
                uint32_t b0h, b1h, b2h, b3h, b0l, b1l, b2l, b3l;
                LDSM4(b0h, b1h, b2h, b3h, base + kst + ko);
                LDSM4(b0l, b1l, b2l, b3l, base + lst + ko);
                uint32_t bhA[2] = {b0h, b1h}, bhB[2] = {b2h, b3h};
                uint32_t blA[2] = {b0l, b1l}, blB[2] = {b2l, b3l};
                mma_f16(s[2*np  ], ah, bhA);
                mma_f16(s[2*np  ], ah, blA);
                mma_f16(s[2*np  ], al, bhA);
                mma_f16(s[2*np+1], ah, bhB);
                mma_f16(s[2*np+1], ah, blB);
                mma_f16(s[2*np+1], al, bhB);
            }
        }

        // ---- online softmax (rows g, g+8; stats across 4 c-lanes) -----------
        #pragma unroll
        for (int hf = 0; hf < 2; hf++) {
            float mx = -1e30f;
            #pragma unroll
            for (int nt = 0; nt < 8; nt++) {
                s[nt][hf*2]   *= 0.125f;
                s[nt][hf*2+1] *= 0.125f;
                mx = fmaxf(mx, fmaxf(s[nt][hf*2], s[nt][hf*2+1]));
            }
            mx = fmaxf(mx, __shfl_xor_sync(0xffffffffu, mx, 1));
            mx = fmaxf(mx, __shfl_xor_sync(0xffffffffu, mx, 2));
            const float mn = fmaxf(mrun[hf], mx);
            const float corr = __expf(mrun[hf] - mn);
            mrun[hf] = mn;
            float ls = 0.f;
            #pragma unroll
            for (int nt = 0; nt < 8; nt++) {
                const float e0 = __expf(s[nt][hf*2]   - mn);
                const float e1 = __expf(s[nt][hf*2+1] - mn);
                s[nt][hf*2] = e0; s[nt][hf*2+1] = e1;
                ls += e0 + e1;
            }
            ls += __shfl_xor_sync(0xffffffffu, ls, 1);
            ls += __shfl_xor_sync(0xffffffffu, ls, 2);
            lrun[hf] = lrun[hf]*corr + ls;
            #pragma unroll
            for (int nt = 0; nt < 8; nt++) {
                o[nt][hf*2]   *= corr;
                o[nt][hf*2+1] *= corr;
            }
        }

        // ---- P fragments directly from acc registers ------------------------
        uint32_t pa[4][4];
        #pragma unroll
        for (int kv = 0; kv < 4; kv++) {
            __half2 h0 = __floats2half2_rn(s[2*kv  ][0], s[2*kv  ][1]);
            __half2 h1 = __floats2half2_rn(s[2*kv  ][2], s[2*kv  ][3]);
            __half2 h2 = __floats2half2_rn(s[2*kv+1][0], s[2*kv+1][1]);
            __half2 h3 = __floats2half2_rn(s[2*kv+1][2], s[2*kv+1][3]);
            pa[kv][0] = *reinterpret_cast<uint32_t*>(&h0);
            pa[kv][1] = *reinterpret_cast<uint32_t*>(&h1);
            pa[kv][2] = *reinterpret_cast<uint32_t*>(&h2);
            pa[kv][3] = *reinterpret_cast<uint32_t*>(&h3);
        }

        // ---- O += P V (V 2-term) --------------------------------------------
        #pragma unroll
        for (int kv = 0; kv < 4; kv++) {
            #pragma unroll
            for (int np = 0; np < 4; np++) {
                const uint32_t vo = (uint32_t)(((np*16 + b_ro)*TST + kv*16 + b_co)*2);
                uint32_t v0h, v1h, v2h, v3h, v0l, v1l, v2l, v3l;
                LDSM4(v0h, v1h, v2h, v3h, base + vhst + vo);
                LDSM4(v0l, v1l, v2l, v3l, base + vlst + vo);
                uint32_t vhA[2] = {v0h, v1h}, vhB[2] = {v2h, v3h};
                uint32_t vlA[2] = {v0l, v1l}, vlB[2] = {v2l, v3l};
                mma_f16(o[2*np  ], pa[kv], vhA);
                mma_f16(o[2*np  ], pa[kv], vlA);
                mma_f16(o[2*np+1], pa[kv], vhB);
                mma_f16(o[2*np+1], pa[kv], vlB);
            }
        }
        __syncthreads();
    }

    // epilogue: normalize, split, store hi/lo planes for the O-GEMM
    #pragma unroll
    for (int hf = 0; hf < 2; hf++) {
        const int r = q0 + wr + g + hf*8;
        const float inv = 1.f / lrun[hf];
        #pragma unroll
        for (int nt = 0; nt < 8; nt++) {
            const int col = h*DK_ + nt*8 + c*2;
            uint32_t h2, l2;
            split2(o[nt][hf*2]*inv, o[nt][hf*2+1]*inv, h2, l2);
            const size_t off = (((size_t)b*S_ + r)*D_ + col) >> 1;
            ((uint32_t*)g_aph)[off] = h2;
            ((uint32_t*)g_apl)[off] = l2;
        }
    }
}

// ---------------- launch ------------------------------------------------------
extern "C" void kernel_launch(void* const* d_in, const int* in_sizes, int n_in,
                              void* d_out, int out_size)
{
    (void)in_sizes; (void)n_in; (void)out_size;
    const float* Q  = (const float*)d_in[0];
    const float* K  = (const float*)d_in[1];
    const float* V  = (const float*)d_in[2];
    const float* Wq = (const float*)d_in[3];
    const float* bq = (const float*)d_in[4];
    const float* Wk = (const float*)d_in[5];
    const float* bk = (const float*)d_in[6];
    const float* Wv = (const float*)d_in[7];
    const float* bv = (const float*)d_in[8];
    const float* Wo = (const float*)d_in[9];
    const float* bo = (const float*)d_in[10];
    float* out = (float*)d_out;

    cudaFuncSetAttribute(gemm_qkv, cudaFuncAttributeMaxDynamicSharedMemorySize, GEMM_SMEM);
    cudaFuncSetAttribute(gemm_out, cudaFuncAttributeMaxDynamicSharedMemorySize, GEMM_SMEM);
    cudaFuncSetAttribute(attn_f16, cudaFuncAttributeMaxDynamicSharedMemorySize, ATTN_SMEM);

    split_all<<<dim3(4096, 7), 256>>>((const float4*)Q,  (const float4*)K,
                                      (const float4*)V,  (const float4*)Wq,
                                      (const float4*)Wk, (const float4*)Wv,
                                      (const float4*)Wo);

    gemm_qkv<<<dim3(M_/128, D_/128, 3), 256, GEMM_SMEM>>>(bq, bk, bv);

    attn_f16<<<dim3(S_/128, H_, B_), 256, ATTN_SMEM>>>();

    gemm_out<<<dim3(M_/128, D_/128), 256, GEMM_SMEM>>>(bo, out);
}